// round 13
// baseline (speedup 1.0000x reference)
#include <cuda_runtime.h>
#include <cuda_bf16.h>
#include <cstdint>

#define INPUT_DIM 16384
#define EMB 1024
#define BATCH 4096
#define XS_N (INPUT_DIM + EMB * 3)   // 19456 floats, pad-4 bound (<32768, fits 15 bits)

#define GTHREADS 512
#define GRID_G   296                 // 2 CTAs/SM x 148 SMs, single persistent wave

// ---------------- device scratch ----------------
__device__ unsigned short g_comb[INPUT_DIM];                 // e | (neg<<15) per feature j
__device__ __align__(16) unsigned short g_pos[INPUT_DIM];    // slot | (neg<<15), by j
__device__ int g_astart[EMB];                                // pad-4 bucket start
__device__ int g_len[EMB];                                   // actual bucket length

// ---------------- K1: extract — 2 rows per warp for 2x MLP on the 2-round chain ----------------
__global__ void k_extract(const float* __restrict__ hp) {
    int warp = (blockIdx.x * blockDim.x + threadIdx.x) >> 5;   // 0..8191
    int lane = threadIdx.x & 31;
    int rA = warp * 2, rB = warp * 2 + 1;
    if (rA >= INPUT_DIM) return;

    const float4* rowA = reinterpret_cast<const float4*>(hp + (size_t)rA * EMB);
    const float4* rowB = reinterpret_cast<const float4*>(hp + (size_t)rB * EMB);
    float4 ca[4], cb[4];
    int eA = 0, eB = 0; unsigned nA = 0, nB = 0; bool hA = false, hB = false;

#pragma unroll
    for (int i = 0; i < 4; i++) { ca[i] = rowA[lane + i * 32]; cb[i] = rowB[lane + i * 32]; }
#pragma unroll
    for (int i = 0; i < 4; i++) {
        int base = (lane + i * 32) * 4;
        if (ca[i].x != 0.0f) { eA = base + 0; nA = (ca[i].x < 0.0f); hA = true; }
        if (ca[i].y != 0.0f) { eA = base + 1; nA = (ca[i].y < 0.0f); hA = true; }
        if (ca[i].z != 0.0f) { eA = base + 2; nA = (ca[i].z < 0.0f); hA = true; }
        if (ca[i].w != 0.0f) { eA = base + 3; nA = (ca[i].w < 0.0f); hA = true; }
        if (cb[i].x != 0.0f) { eB = base + 0; nB = (cb[i].x < 0.0f); hB = true; }
        if (cb[i].y != 0.0f) { eB = base + 1; nB = (cb[i].y < 0.0f); hB = true; }
        if (cb[i].z != 0.0f) { eB = base + 2; nB = (cb[i].z < 0.0f); hB = true; }
        if (cb[i].w != 0.0f) { eB = base + 3; nB = (cb[i].w < 0.0f); hB = true; }
    }
    unsigned mA = __ballot_sync(0xffffffffu, hA);
    unsigned mB = __ballot_sync(0xffffffffu, hB);

    if (!(mA && mB)) {
        bool needA = (mA == 0), needB = (mB == 0);
        if (needA) {
#pragma unroll
            for (int i = 0; i < 4; i++) ca[i] = rowA[lane + (i + 4) * 32];
        }
        if (needB) {
#pragma unroll
            for (int i = 0; i < 4; i++) cb[i] = rowB[lane + (i + 4) * 32];
        }
#pragma unroll
        for (int i = 0; i < 4; i++) {
            int base = (lane + (i + 4) * 32) * 4;
            if (needA) {
                if (ca[i].x != 0.0f) { eA = base + 0; nA = (ca[i].x < 0.0f); hA = true; }
                if (ca[i].y != 0.0f) { eA = base + 1; nA = (ca[i].y < 0.0f); hA = true; }
                if (ca[i].z != 0.0f) { eA = base + 2; nA = (ca[i].z < 0.0f); hA = true; }
                if (ca[i].w != 0.0f) { eA = base + 3; nA = (ca[i].w < 0.0f); hA = true; }
            }
            if (needB) {
                if (cb[i].x != 0.0f) { eB = base + 0; nB = (cb[i].x < 0.0f); hB = true; }
                if (cb[i].y != 0.0f) { eB = base + 1; nB = (cb[i].y < 0.0f); hB = true; }
                if (cb[i].z != 0.0f) { eB = base + 2; nB = (cb[i].z < 0.0f); hB = true; }
                if (cb[i].w != 0.0f) { eB = base + 3; nB = (cb[i].w < 0.0f); hB = true; }
            }
        }
        mA = __ballot_sync(0xffffffffu, hA);
        mB = __ballot_sync(0xffffffffu, hB);
    }

    {
        int src = mA ? (__ffs(mA) - 1) : 0;
        int e        = __shfl_sync(0xffffffffu, eA, src);
        unsigned neg = __shfl_sync(0xffffffffu, nA, src);
        if (lane == 0) g_comb[rA] = mA ? (unsigned short)(e | (neg << 15)) : 0;
    }
    {
        int src = mB ? (__ffs(mB) - 1) : 0;
        int e        = __shfl_sync(0xffffffffu, eB, src);
        unsigned neg = __shfl_sync(0xffffffffu, nB, src);
        if (lane == 0) g_comb[rB] = mB ? (unsigned short)(e | (neg << 15)) : 0;
    }
}

// ---------------- K2: build — histogram, scan, then BANK-AWARE slot matching ----------------
// Store-group structure mirrors k_gather's scatter: group (w,i,k) = lanes l of
// warp w writing component k of float4 quad (32w+l+512i). One build thread per
// group greedily claims, for each of its 32 features, a free within-bucket
// position whose bank (slot&31) is not yet used in the group.
__global__ __launch_bounds__(512, 1)
void k_build() {
    __shared__ int hist[EMB];
    __shared__ int sa[EMB];                // bucket starts (smem copy)
    __shared__ unsigned fl[EMB], fh[EMB];  // free-position bitmasks (pos 0-31, 32-63)
    __shared__ int wsum[16];
    int t = threadIdx.x;
    int lane = t & 31, w = t >> 5;

    hist[t] = 0; hist[t + 512] = 0;
    __syncthreads();
#pragma unroll
    for (int i = 0; i < INPUT_DIM / 512; i++)
        atomicAdd(&hist[g_comb[i * 512 + t] & (EMB - 1)], 1);
    __syncthreads();

    int c0 = hist[t], c1 = hist[t + 512];
    int p0 = (c0 + 3) & ~3, p1 = (c1 + 3) & ~3;
    int pair = p0 + p1;

    // inclusive scan over 512 threads
    int s = pair;
#pragma unroll
    for (int off = 1; off < 32; off <<= 1) {
        int n = __shfl_up_sync(0xffffffffu, s, off);
        if (lane >= off) s += n;
    }
    if (lane == 31) wsum[w] = s;
    __syncthreads();
    if (w == 0 && lane < 16) {
        int sv = wsum[lane];
#pragma unroll
        for (int off = 1; off < 16; off <<= 1) {
            int n = __shfl_up_sync(0xffffu, sv, off);
            if (lane >= off) sv += n;
        }
        wsum[lane] = sv;
    }
    __syncthreads();
    int excl = s - pair + (w > 0 ? wsum[w - 1] : 0);

    sa[t] = excl;            g_astart[t] = excl;            g_len[t] = c0;
    sa[t + 512] = excl + p0; g_astart[t + 512] = excl + p0; g_len[t + 512] = c1;
    fl[t] = (c0 >= 32) ? 0xffffffffu : ((1u << c0) - 1u);
    fh[t] = (c0 > 32) ? (((c0 - 32) >= 32) ? 0xffffffffu : ((1u << (c0 - 32)) - 1u)) : 0u;
    fl[t + 512] = (c1 >= 32) ? 0xffffffffu : ((1u << c1) - 1u);
    fh[t + 512] = (c1 > 32) ? (((c1 - 32) >= 32) ? 0xffffffffu : ((1u << (c1 - 32)) - 1u)) : 0u;
    __syncthreads();

    // matching: thread t = group (ww, ii, kk)
    int kk = t & 3, ii = (t >> 2) & 7, ww = t >> 5;
    unsigned used = 0;
#pragma unroll 1
    for (int l = 0; l < 32; l++) {
        int j = 4 * (32 * ww + l + 512 * ii) + kk;
        unsigned cb = g_comb[j];
        int e  = cb & (EMB - 1);
        int s0 = sa[e];
        int sb = s0 & 31;
        int p; unsigned bank;
        for (;;) {
            unsigned flo = fl[e];
            unsigned cand = __funnelshift_l(flo, flo, sb) & ~used;   // achievable banks not yet used
            if (cand) {
                bank = __ffs(cand) - 1;
                p = (int)((bank - sb) & 31u);
                unsigned bit = 1u << p;
                unsigned old = atomicAnd(&fl[e], ~bit);
                if (old & bit) break;
                continue;
            }
            if (flo) {                       // any free low position
                p = __ffs(flo) - 1;
                unsigned bit = 1u << p;
                unsigned old = atomicAnd(&fl[e], ~bit);
                if (old & bit) { bank = (unsigned)((s0 + p) & 31); break; }
                continue;
            }
            unsigned fhi = fh[e];
            if (fhi) {                       // high positions (len > 32)
                int ph = __ffs(fhi) - 1;
                unsigned bit = 1u << ph;
                unsigned old = atomicAnd(&fh[e], ~bit);
                if (old & bit) { p = 32 + ph; bank = (unsigned)((s0 + p) & 31); break; }
                continue;
            }
            // counting argument: impossible; loop retries on transient race
        }
        used |= (1u << bank);
        g_pos[j] = (unsigned short)((s0 + p) | (cb & 0x8000u));
    }
}

// ---------------- K3: persistent pipelined gather (R11 champion, unchanged) ----------------
__global__ __launch_bounds__(GTHREADS, 2)
void k_gather(const float* __restrict__ x, float* __restrict__ out) {
    extern __shared__ float xs[];          // [XS_N]
    int t = threadIdx.x;

    int s0a = __ldg(&g_astart[t]);
    int la  = __ldg(&g_len[t]);
    int s0b = __ldg(&g_astart[t + GTHREADS]);
    int lb  = __ldg(&g_len[t + GTHREADS]);

    uint2 q[8];
    {
        const uint2* gp = reinterpret_cast<const uint2*>(g_pos);
#pragma unroll
        for (int i = 0; i < 8; i++) q[i] = gp[t + i * GTHREADS];
    }

    // zero pad slots once (scatter never writes pads)
    {
        int pa = (la + 3) & ~3;
        for (int k = s0a + la; k < s0a + pa; k++) xs[k] = 0.0f;
        int pb = (lb + 3) & ~3;
        for (int k = s0b + lb; k < s0b + pb; k++) xs[k] = 0.0f;
    }

    int n4a = ((la + 3) & ~3) >> 2;
    int n4b = ((lb + 3) & ~3) >> 2;

    int b = blockIdx.x;
    float4 v[8];
    if (b < BATCH) {
        const float4* gx = reinterpret_cast<const float4*>(x + (size_t)b * INPUT_DIM);
#pragma unroll
        for (int i = 0; i < 8; i++) v[i] = gx[t + i * GTHREADS];
    }

    for (; b < BATCH; b += GRID_G) {
        __syncthreads();

#pragma unroll
        for (int i = 0; i < 8; i++) {
            unsigned q0 = q[i].x & 0xFFFFu, q1 = q[i].x >> 16;
            unsigned q2 = q[i].y & 0xFFFFu, q3 = q[i].y >> 16;
            xs[q0 & 0x7FFFu] = __uint_as_float(__float_as_uint(v[i].x) ^ ((q0 & 0x8000u) << 16));
            xs[q1 & 0x7FFFu] = __uint_as_float(__float_as_uint(v[i].y) ^ ((q1 & 0x8000u) << 16));
            xs[q2 & 0x7FFFu] = __uint_as_float(__float_as_uint(v[i].z) ^ ((q2 & 0x8000u) << 16));
            xs[q3 & 0x7FFFu] = __uint_as_float(__float_as_uint(v[i].w) ^ ((q3 & 0x8000u) << 16));
        }

        int bn = b + GRID_G;
        if (bn < BATCH) {
            const float4* gx = reinterpret_cast<const float4*>(x + (size_t)bn * INPUT_DIM);
#pragma unroll
            for (int i = 0; i < 8; i++) v[i] = gx[t + i * GTHREADS];
        }

        __syncthreads();

        float* o = out + (size_t)b * EMB;
        {
            const float4* xs4 = reinterpret_cast<const float4*>(xs) + (s0a >> 2);
            float acc = 0.0f;
            for (int i = 0; i < n4a; i++) {
                float4 u = xs4[i];
                acc += (u.x + u.y) + (u.z + u.w);
            }
            o[t] = acc;
        }
        {
            const float4* xs4 = reinterpret_cast<const float4*>(xs) + (s0b >> 2);
            float acc = 0.0f;
            for (int i = 0; i < n4b; i++) {
                float4 u = xs4[i];
                acc += (u.x + u.y) + (u.z + u.w);
            }
            o[t + GTHREADS] = acc;
        }
    }
}

extern "C" void kernel_launch(void* const* d_in, const int* in_sizes, int n_in,
                              void* d_out, int out_size) {
    const float* x  = (const float*)d_in[0];   // [BATCH, INPUT_DIM]
    const float* hp = (const float*)d_in[1];   // [INPUT_DIM, EMB]
    float* out = (float*)d_out;                // [BATCH, EMB]

    int smem = XS_N * (int)sizeof(float);      // 77824 B -> 2 blocks/SM
    cudaFuncSetAttribute(k_gather, cudaFuncAttributeMaxDynamicSharedMemorySize, smem);

    k_extract<<<(INPUT_DIM / 2 * 32) / 256, 256>>>(hp);
    k_build<<<1, 512>>>();
    k_gather<<<GRID_G, GTHREADS, smem>>>(x, out);
}

// round 14
// speedup vs baseline: 1.0805x; 1.0805x over previous
#include <cuda_runtime.h>
#include <cuda_bf16.h>
#include <cstdint>

#define INPUT_DIM 16384
#define EMB 1024
#define BATCH 4096
#define XS_N (INPUT_DIM + EMB * 3)   // 19456 floats, pad-4 bound (<32768, fits 15 bits)

#define GRID_G 148                   // 1 CTA/SM, warp-specialized

// ---------------- device scratch ----------------
__device__ unsigned short g_comb[INPUT_DIM];                 // e | (neg<<15) per feature j
__device__ __align__(16) unsigned short g_pos[INPUT_DIM];    // slot | (neg<<15), by j
__device__ int g_astart[EMB];                                // pad-4 bucket start
__device__ int g_len[EMB];                                   // actual bucket length

// ---------------- K1: extract (R11 champion version: 1 row/warp, 2-round prefetch) ----------------
__global__ void k_extract(const float* __restrict__ hp) {
    int warp = (blockIdx.x * blockDim.x + threadIdx.x) >> 5;
    int lane = threadIdx.x & 31;
    if (warp >= INPUT_DIM) return;

    const float4* row = reinterpret_cast<const float4*>(hp + (size_t)warp * EMB);
    float4 c[4];
    int my_e = 0; unsigned my_neg = 0; bool has = false;

#pragma unroll
    for (int i = 0; i < 4; i++) c[i] = row[lane + i * 32];
#pragma unroll
    for (int i = 0; i < 4; i++) {
        int base = (lane + i * 32) * 4;
        if (c[i].x != 0.0f) { my_e = base + 0; my_neg = (c[i].x < 0.0f); has = true; }
        if (c[i].y != 0.0f) { my_e = base + 1; my_neg = (c[i].y < 0.0f); has = true; }
        if (c[i].z != 0.0f) { my_e = base + 2; my_neg = (c[i].z < 0.0f); has = true; }
        if (c[i].w != 0.0f) { my_e = base + 3; my_neg = (c[i].w < 0.0f); has = true; }
    }
    unsigned mask = __ballot_sync(0xffffffffu, has);

    if (mask == 0) {
#pragma unroll
        for (int i = 0; i < 4; i++) c[i] = row[lane + (i + 4) * 32];
#pragma unroll
        for (int i = 0; i < 4; i++) {
            int base = (lane + (i + 4) * 32) * 4;
            if (c[i].x != 0.0f) { my_e = base + 0; my_neg = (c[i].x < 0.0f); has = true; }
            if (c[i].y != 0.0f) { my_e = base + 1; my_neg = (c[i].y < 0.0f); has = true; }
            if (c[i].z != 0.0f) { my_e = base + 2; my_neg = (c[i].z < 0.0f); has = true; }
            if (c[i].w != 0.0f) { my_e = base + 3; my_neg = (c[i].w < 0.0f); has = true; }
        }
        mask = __ballot_sync(0xffffffffu, has);
    }

    if (mask == 0) { if (lane == 0) g_comb[warp] = 0; return; }
    int src = __ffs(mask) - 1;
    int e        = __shfl_sync(0xffffffffu, my_e, src);
    unsigned neg = __shfl_sync(0xffffffffu, my_neg, src);
    if (lane == 0) g_comb[warp] = (unsigned short)(e | (neg << 15));
}

// ---------------- K2: fused build (R11 version) ----------------
__global__ __launch_bounds__(EMB, 1)
void k_build() {
    __shared__ int hist[EMB];
    __shared__ int cur[EMB];
    __shared__ int wsum[32];
    int t = threadIdx.x;
    int lane = t & 31, w = t >> 5;

    hist[t] = 0;
    __syncthreads();

#pragma unroll
    for (int i = 0; i < INPUT_DIM / EMB; i++)
        atomicAdd(&hist[g_comb[i * EMB + t] & (EMB - 1)], 1);
    __syncthreads();

    int c  = hist[t];
    int pl = (c + 3) & ~3;

    int v = pl;
#pragma unroll
    for (int off = 1; off < 32; off <<= 1) {
        int n = __shfl_up_sync(0xffffffffu, v, off);
        if (lane >= off) v += n;
    }
    if (lane == 31) wsum[w] = v;
    __syncthreads();
    if (w == 0) {
        int s = wsum[lane];
#pragma unroll
        for (int off = 1; off < 32; off <<= 1) {
            int n = __shfl_up_sync(0xffffffffu, s, off);
            if (lane >= off) s += n;
        }
        wsum[lane] = s;
    }
    __syncthreads();
    int incl  = v + (w > 0 ? wsum[w - 1] : 0);
    int start = incl - pl;
    g_astart[t] = start;
    g_len[t]    = c;
    cur[t]      = start;
    __syncthreads();

#pragma unroll
    for (int i = 0; i < INPUT_DIM / EMB; i++) {
        int j = i * EMB + t;
        unsigned cb = g_comb[j];
        int pos = atomicAdd(&cur[cb & (EMB - 1)], 1);
        g_pos[j] = (unsigned short)(pos | (cb & 0x8000u));
    }
}

// ---------------- K3: warp-specialized producer/consumer gather, double buffer ----------------
// warps 0-15 (t<512): producers — LDG x row, scatter into buf[k&1]
// warps 16-31       : consumers — reduce buf[k&1], store out
// named barriers: FULL_b = 1+b (prod arrive, cons sync); EMPTY_b = 3+b (cons arrive, prod sync)
#define BAR_SYNC(id)   asm volatile("bar.sync %0, 1024;"   :: "r"(id) : "memory")
#define BAR_ARRIVE(id) asm volatile("bar.arrive %0, 1024;" :: "r"(id) : "memory")

__global__ __launch_bounds__(1024, 1)
void k_gather(const float* __restrict__ x, float* __restrict__ out) {
    extern __shared__ float xs[];          // [2][XS_N]
    int t = threadIdx.x;

    // zero pad slots once, in both buffers
    for (int e = t; e < EMB; e += 1024) {
        int s0 = __ldg(&g_astart[e]);
        int l  = __ldg(&g_len[e]);
        int pl = (l + 3) & ~3;
        for (int k = s0 + l; k < s0 + pl; k++) { xs[k] = 0.0f; xs[XS_N + k] = 0.0f; }
    }
    __syncthreads();

    if (t < 512) {
        // ---------------- producer ----------------
        uint2 q[8];
        {
            const uint2* gp = reinterpret_cast<const uint2*>(g_pos);
#pragma unroll
            for (int i = 0; i < 8; i++) q[i] = gp[t + i * 512];
        }
        float4 v[8];
        int b = blockIdx.x;
        {
            const float4* gx = reinterpret_cast<const float4*>(x + (size_t)b * INPUT_DIM);
#pragma unroll
            for (int i = 0; i < 8; i++) v[i] = gx[t + i * 512];
        }
        int k = 0;
        for (; b < BATCH; b += GRID_G, k++) {
            int br = k & 1;
            if (k >= 2) BAR_SYNC(3 + br);          // wait EMPTY_br
            float* buf = xs + br * XS_N;
#pragma unroll
            for (int i = 0; i < 8; i++) {
                unsigned q0 = q[i].x & 0xFFFFu, q1 = q[i].x >> 16;
                unsigned q2 = q[i].y & 0xFFFFu, q3 = q[i].y >> 16;
                buf[q0 & 0x7FFFu] = __uint_as_float(__float_as_uint(v[i].x) ^ ((q0 & 0x8000u) << 16));
                buf[q1 & 0x7FFFu] = __uint_as_float(__float_as_uint(v[i].y) ^ ((q1 & 0x8000u) << 16));
                buf[q2 & 0x7FFFu] = __uint_as_float(__float_as_uint(v[i].z) ^ ((q2 & 0x8000u) << 16));
                buf[q3 & 0x7FFFu] = __uint_as_float(__float_as_uint(v[i].w) ^ ((q3 & 0x8000u) << 16));
            }
            // issue next row's loads — DRAM streams through handshakes + consumer reduce
            int bn = b + GRID_G;
            if (bn < BATCH) {
                const float4* gx = reinterpret_cast<const float4*>(x + (size_t)bn * INPUT_DIM);
#pragma unroll
                for (int i = 0; i < 8; i++) v[i] = gx[t + i * 512];
            }
            __threadfence_block();                 // make STS visible before release
            BAR_ARRIVE(1 + br);                    // signal FULL_br
        }
    } else {
        // ---------------- consumer ----------------
        int ct  = t - 512;
        int s0a = __ldg(&g_astart[ct]);
        int la  = __ldg(&g_len[ct]);
        int s0b = __ldg(&g_astart[ct + 512]);
        int lb  = __ldg(&g_len[ct + 512]);
        int n4a = ((la + 3) & ~3) >> 2;
        int n4b = ((lb + 3) & ~3) >> 2;

        int k = 0;
        for (int b = blockIdx.x; b < BATCH; b += GRID_G, k++) {
            int br = k & 1;
            BAR_SYNC(1 + br);                      // wait FULL_br
            const float* buf = xs + br * XS_N;
            float* o = out + (size_t)b * EMB;
            {
                const float4* xs4 = reinterpret_cast<const float4*>(buf) + (s0a >> 2);
                float acc = 0.0f;
                for (int i = 0; i < n4a; i++) {
                    float4 u = xs4[i];
                    acc += (u.x + u.y) + (u.z + u.w);
                }
                o[ct] = acc;
            }
            {
                const float4* xs4 = reinterpret_cast<const float4*>(buf) + (s0b >> 2);
                float acc = 0.0f;
                for (int i = 0; i < n4b; i++) {
                    float4 u = xs4[i];
                    acc += (u.x + u.y) + (u.z + u.w);
                }
                o[ct + 512] = acc;
            }
            BAR_ARRIVE(3 + br);                    // signal EMPTY_br
        }
    }
}

extern "C" void kernel_launch(void* const* d_in, const int* in_sizes, int n_in,
                              void* d_out, int out_size) {
    const float* x  = (const float*)d_in[0];   // [BATCH, INPUT_DIM]
    const float* hp = (const float*)d_in[1];   // [INPUT_DIM, EMB]
    float* out = (float*)d_out;                // [BATCH, EMB]

    int smem = 2 * XS_N * (int)sizeof(float);  // 155648 B -> 1 CTA/SM
    cudaFuncSetAttribute(k_gather, cudaFuncAttributeMaxDynamicSharedMemorySize, smem);

    k_extract<<<(INPUT_DIM * 32) / 256, 256>>>(hp);
    k_build<<<1, EMB>>>();
    k_gather<<<GRID_G, 1024, smem>>>(x, out);
}

// round 16
// speedup vs baseline: 1.1136x; 1.0307x over previous
#include <cuda_runtime.h>
#include <cuda_bf16.h>
#include <cstdint>

#define INPUT_DIM 16384
#define EMB 1024
#define BATCH 4096
#define XS_N (INPUT_DIM + EMB * 3)   // 19456 floats, pad-4 bound (<32768, fits 15 bits)

#define GTHREADS 512
#define GRID_G   296                 // 2 CTAs/SM x 148 SMs, single persistent wave

// ---------------- device scratch ----------------
__device__ unsigned short g_comb[INPUT_DIM];                 // e | (neg<<15) per feature j
__device__ __align__(16) unsigned short g_pos[INPUT_DIM];    // slot | (neg<<15), by j
__device__ int g_astart[EMB];                                // pad-4 bucket start
__device__ int g_len[EMB];                                   // actual bucket length

// ---------------- K1: extract (R11 champion: 1 row/warp, 2-round batched prefetch) ----------------
__global__ void k_extract(const float* __restrict__ hp) {
    int warp = (blockIdx.x * blockDim.x + threadIdx.x) >> 5;
    int lane = threadIdx.x & 31;
    if (warp >= INPUT_DIM) return;

    const float4* row = reinterpret_cast<const float4*>(hp + (size_t)warp * EMB);
    float4 c[4];
    int my_e = 0; unsigned my_neg = 0; bool has = false;

#pragma unroll
    for (int i = 0; i < 4; i++) c[i] = row[lane + i * 32];
#pragma unroll
    for (int i = 0; i < 4; i++) {
        int base = (lane + i * 32) * 4;
        if (c[i].x != 0.0f) { my_e = base + 0; my_neg = (c[i].x < 0.0f); has = true; }
        if (c[i].y != 0.0f) { my_e = base + 1; my_neg = (c[i].y < 0.0f); has = true; }
        if (c[i].z != 0.0f) { my_e = base + 2; my_neg = (c[i].z < 0.0f); has = true; }
        if (c[i].w != 0.0f) { my_e = base + 3; my_neg = (c[i].w < 0.0f); has = true; }
    }
    unsigned mask = __ballot_sync(0xffffffffu, has);

    if (mask == 0) {
#pragma unroll
        for (int i = 0; i < 4; i++) c[i] = row[lane + (i + 4) * 32];
#pragma unroll
        for (int i = 0; i < 4; i++) {
            int base = (lane + (i + 4) * 32) * 4;
            if (c[i].x != 0.0f) { my_e = base + 0; my_neg = (c[i].x < 0.0f); has = true; }
            if (c[i].y != 0.0f) { my_e = base + 1; my_neg = (c[i].y < 0.0f); has = true; }
            if (c[i].z != 0.0f) { my_e = base + 2; my_neg = (c[i].z < 0.0f); has = true; }
            if (c[i].w != 0.0f) { my_e = base + 3; my_neg = (c[i].w < 0.0f); has = true; }
        }
        mask = __ballot_sync(0xffffffffu, has);
    }

    if (mask == 0) { if (lane == 0) g_comb[warp] = 0; return; }
    int src = __ffs(mask) - 1;
    int e        = __shfl_sync(0xffffffffu, my_e, src);
    unsigned neg = __shfl_sync(0xffffffffu, my_neg, src);
    if (lane == 0) g_comb[warp] = (unsigned short)(e | (neg << 15));
}

// ---------------- K2: fused build (R11 version, separate kernel — no barriers) ----------------
__global__ __launch_bounds__(EMB, 1)
void k_build() {
    __shared__ int hist[EMB];
    __shared__ int cur[EMB];
    __shared__ int wsum[32];
    int t = threadIdx.x;
    int lane = t & 31, w = t >> 5;

    hist[t] = 0;
    __syncthreads();

#pragma unroll
    for (int i = 0; i < INPUT_DIM / EMB; i++)
        atomicAdd(&hist[g_comb[i * EMB + t] & (EMB - 1)], 1);
    __syncthreads();

    int c  = hist[t];
    int pl = (c + 3) & ~3;

    int v = pl;
#pragma unroll
    for (int off = 1; off < 32; off <<= 1) {
        int n = __shfl_up_sync(0xffffffffu, v, off);
        if (lane >= off) v += n;
    }
    if (lane == 31) wsum[w] = v;
    __syncthreads();
    if (w == 0) {
        int s = wsum[lane];
#pragma unroll
        for (int off = 1; off < 32; off <<= 1) {
            int n = __shfl_up_sync(0xffffffffu, s, off);
            if (lane >= off) s += n;
        }
        wsum[lane] = s;
    }
    __syncthreads();
    int incl  = v + (w > 0 ? wsum[w - 1] : 0);
    int start = incl - pl;
    g_astart[t] = start;
    g_len[t]    = c;
    cur[t]      = start;
    __syncthreads();

#pragma unroll
    for (int i = 0; i < INPUT_DIM / EMB; i++) {
        int j = i * EMB + t;
        unsigned cb = g_comb[j];
        int pos = atomicAdd(&cur[cb & (EMB - 1)], 1);
        g_pos[j] = (unsigned short)(pos | (cb & 0x8000u));
    }
}

// ---------------- K3: persistent gather with HALF-SPLIT load/scatter pipeline ----------------
__global__ __launch_bounds__(GTHREADS, 2)
void k_gather(const float* __restrict__ x, float* __restrict__ out) {
    extern __shared__ float xs[];          // [XS_N]
    int t = threadIdx.x;

    int s0a = __ldg(&g_astart[t]);
    int la  = __ldg(&g_len[t]);
    int s0b = __ldg(&g_astart[t + GTHREADS]);
    int lb  = __ldg(&g_len[t + GTHREADS]);

    uint2 q[8];
    {
        const uint2* gp = reinterpret_cast<const uint2*>(g_pos);
#pragma unroll
        for (int i = 0; i < 8; i++) q[i] = gp[t + i * GTHREADS];
    }

    // zero pad slots once (scatter never writes pads)
    {
        int pa = (la + 3) & ~3;
        for (int k = s0a + la; k < s0a + pa; k++) xs[k] = 0.0f;
        int pb = (lb + 3) & ~3;
        for (int k = s0b + lb; k < s0b + pb; k++) xs[k] = 0.0f;
    }

    int n4a = ((la + 3) & ~3) >> 2;
    int n4b = ((lb + 3) & ~3) >> 2;

    // first-row prefetch (both halves)
    int b = blockIdx.x;
    float4 vlo[4], vhi[4];
    if (b < BATCH) {
        const float4* gx = reinterpret_cast<const float4*>(x + (size_t)b * INPUT_DIM);
#pragma unroll
        for (int i = 0; i < 4; i++) vlo[i] = gx[t + i * GTHREADS];
#pragma unroll
        for (int i = 0; i < 4; i++) vhi[i] = gx[t + (i + 4) * GTHREADS];
    }

    for (; b < BATCH; b += GRID_G) {
        __syncthreads();                   // pads ready / prev reduce done reading xs
        int bn = b + GRID_G;
        const float4* gxn = reinterpret_cast<const float4*>(x + (size_t)bn * INPUT_DIM);

        // scatter lo half of row b, then immediately issue lo half of row bn
#pragma unroll
        for (int i = 0; i < 4; i++) {
            unsigned q0 = q[i].x & 0xFFFFu, q1 = q[i].x >> 16;
            unsigned q2 = q[i].y & 0xFFFFu, q3 = q[i].y >> 16;
            xs[q0 & 0x7FFFu] = __uint_as_float(__float_as_uint(vlo[i].x) ^ ((q0 & 0x8000u) << 16));
            xs[q1 & 0x7FFFu] = __uint_as_float(__float_as_uint(vlo[i].y) ^ ((q1 & 0x8000u) << 16));
            xs[q2 & 0x7FFFu] = __uint_as_float(__float_as_uint(vlo[i].z) ^ ((q2 & 0x8000u) << 16));
            xs[q3 & 0x7FFFu] = __uint_as_float(__float_as_uint(vlo[i].w) ^ ((q3 & 0x8000u) << 16));
        }
        if (bn < BATCH) {
#pragma unroll
            for (int i = 0; i < 4; i++) vlo[i] = gxn[t + i * GTHREADS];
        }

        // scatter hi half of row b, then issue hi half of row bn
#pragma unroll
        for (int i = 0; i < 4; i++) {
            unsigned q0 = q[i + 4].x & 0xFFFFu, q1 = q[i + 4].x >> 16;
            unsigned q2 = q[i + 4].y & 0xFFFFu, q3 = q[i + 4].y >> 16;
            xs[q0 & 0x7FFFu] = __uint_as_float(__float_as_uint(vhi[i].x) ^ ((q0 & 0x8000u) << 16));
            xs[q1 & 0x7FFFu] = __uint_as_float(__float_as_uint(vhi[i].y) ^ ((q1 & 0x8000u) << 16));
            xs[q2 & 0x7FFFu] = __uint_as_float(__float_as_uint(vhi[i].z) ^ ((q2 & 0x8000u) << 16));
            xs[q3 & 0x7FFFu] = __uint_as_float(__float_as_uint(vhi[i].w) ^ ((q3 & 0x8000u) << 16));
        }
        if (bn < BATCH) {
#pragma unroll
            for (int i = 0; i < 4; i++) vhi[i] = gxn[t + (i + 4) * GTHREADS];
        }

        __syncthreads();                   // scatter visible

        // reduce: buckets t and t+512, contiguous float4 streams
        float* o = out + (size_t)b * EMB;
        {
            const float4* xs4 = reinterpret_cast<const float4*>(xs) + (s0a >> 2);
            float acc = 0.0f;
            for (int i = 0; i < n4a; i++) {
                float4 u = xs4[i];
                acc += (u.x + u.y) + (u.z + u.w);
            }
            o[t] = acc;
        }
        {
            const float4* xs4 = reinterpret_cast<const float4*>(xs) + (s0b >> 2);
            float acc = 0.0f;
            for (int i = 0; i < n4b; i++) {
                float4 u = xs4[i];
                acc += (u.x + u.y) + (u.z + u.w);
            }
            o[t + GTHREADS] = acc;
        }
    }
}

extern "C" void kernel_launch(void* const* d_in, const int* in_sizes, int n_in,
                              void* d_out, int out_size) {
    const float* x  = (const float*)d_in[0];   // [BATCH, INPUT_DIM]
    const float* hp = (const float*)d_in[1];   // [INPUT_DIM, EMB]
    float* out = (float*)d_out;                // [BATCH, EMB]

    int smem = XS_N * (int)sizeof(float);      // 77824 B -> 2 blocks/SM
    cudaFuncSetAttribute(k_gather, cudaFuncAttributeMaxDynamicSharedMemorySize, smem);

    k_extract<<<(INPUT_DIM * 32) / 256, 256>>>(hp);
    k_build<<<1, EMB>>>();
    k_gather<<<GRID_G, GTHREADS, smem>>>(x, out);
}